// round 1
// baseline (speedup 1.0000x reference)
#include <cuda_runtime.h>
#include <math.h>

// Problem constants
#define BB 2
#define NN 128
#define HH 2
#define DM 512
#define DK 256
#define BHN (BB*HH*NN)      // 512
#define SCALE 0.005524271728019903f  // 1/sqrt(N*DK) = 1/sqrt(32768)
#define OUT_ELEMS (BB*NN*NN*DM)      // 16777216

// Scratch (device globals; no allocation allowed)
__device__ float g_q[BHN*DK];        // (b,h,n,dk)
__device__ float g_k[BHN*DK];
__device__ float g_v[BHN*DK];
__device__ float g_bx[BB*NN*DK];     // (b,n,dk)
__device__ float g_A[BHN];
__device__ float g_Bq[BHN];
__device__ float g_Ck[BHN];
__device__ float g_Dd[BB*NN];
__device__ float g_S0[BB*HH];
__device__ float g_attn[BB*HH*NN*NN];
__device__ float g_Vw[BHN*2*DM];     // [(b,h,j)][hp][o]
__device__ float g_Bw[BB*NN*2*DM];   // [(b,j)][hp][o]

// ---------------------------------------------------------------------------
// Generic tiled fp32 GEMM: out = A(rows x K) @ W(K x ncol) + bias
// 64x64 tile, 256 threads, 4x4 per thread.
// qkv != 0: store with (b,h,n,dk) permutation (rows=256 -> b,n; col -> h,dk)
// else:     out[row*ostride + col]
// ---------------------------------------------------------------------------
__global__ void gemm_kernel(const float* __restrict__ A,
                            const float* __restrict__ W,
                            const float* __restrict__ bias,
                            int K, int ncol,
                            float* __restrict__ out, int ostride, int qkv)
{
    __shared__ float sA[64][17];
    __shared__ float sB[16][64];
    int t  = threadIdx.x;
    int tx = t & 15, ty = t >> 4;
    int row0 = blockIdx.y * 64;
    int col0 = blockIdx.x * 64;

    float acc[4][4];
#pragma unroll
    for (int i = 0; i < 4; i++)
#pragma unroll
        for (int j = 0; j < 4; j++) acc[i][j] = 0.f;

    for (int k0 = 0; k0 < K; k0 += 16) {
#pragma unroll
        for (int l = 0; l < 4; ++l) {
            int lin = t + l * 256;
            int r = lin >> 4, kk = lin & 15;
            sA[r][kk] = A[(size_t)(row0 + r) * K + k0 + kk];
        }
#pragma unroll
        for (int l = 0; l < 4; ++l) {
            int lin = t + l * 256;
            int kk = lin >> 6, c = lin & 63;
            sB[kk][c] = W[(size_t)(k0 + kk) * ncol + col0 + c];
        }
        __syncthreads();
#pragma unroll
        for (int kk = 0; kk < 16; ++kk) {
            float av[4], bv[4];
#pragma unroll
            for (int i = 0; i < 4; ++i) av[i] = sA[ty * 4 + i][kk];
#pragma unroll
            for (int j = 0; j < 4; ++j) bv[j] = sB[kk][tx * 4 + j];
#pragma unroll
            for (int i = 0; i < 4; ++i)
#pragma unroll
                for (int j = 0; j < 4; ++j)
                    acc[i][j] += av[i] * bv[j];
        }
        __syncthreads();
    }

#pragma unroll
    for (int i = 0; i < 4; ++i) {
        int row = row0 + ty * 4 + i;
#pragma unroll
        for (int j = 0; j < 4; ++j) {
            int col = col0 + tx * 4 + j;
            float val = acc[i][j] + (bias ? bias[col] : 0.f);
            if (qkv) {
                int b = row >> 7, n = row & 127;
                int h = col >> 8, dk = col & 255;
                out[(((b * HH + h) * NN) + n) * DK + dk] = val;
            } else {
                out[(size_t)row * ostride + col] = val;
            }
        }
    }
}

// ---------------------------------------------------------------------------
// Per-(b,h,j) dot products: A = q.k, Bq = bx.k, Ck = q.bx, Dd = bx.bx
// ---------------------------------------------------------------------------
__global__ void dots_kernel()
{
    int bid = blockIdx.x;          // (b*H + h)*N + j
    int j = bid & 127;
    int bh = bid >> 7;
    int b = bh >> 1;
    int t = threadIdx.x;           // 128 threads

    const float* qr = g_q  + (size_t)bid * DK;
    const float* kr = g_k  + (size_t)bid * DK;
    const float* br = g_bx + (size_t)(b * NN + j) * DK;

    float pa = 0.f, pb = 0.f, pc = 0.f, pd = 0.f;
#pragma unroll
    for (int d = t; d < DK; d += 128) {
        float qv = qr[d], kv = kr[d], bv = br[d];
        pa += qv * kv;
        pb += bv * kv;
        pc += qv * bv;
        pd += bv * bv;
    }
    __shared__ float red[4][128];
    red[0][t] = pa; red[1][t] = pb; red[2][t] = pc; red[3][t] = pd;
    __syncthreads();
    for (int s = 64; s > 0; s >>= 1) {
        if (t < s) {
#pragma unroll
            for (int r = 0; r < 4; r++) red[r][t] += red[r][t + s];
        }
        __syncthreads();
    }
    if (t == 0) {
        g_A[bid]  = red[0][0];
        g_Bq[bid] = red[1][0];
        g_Ck[bid] = red[2][0];
        if ((bh & 1) == 0) g_Dd[b * NN + j] = red[3][0];
    }
}

// S0[bh] = sum_j A[bh, j]
__global__ void s0_kernel()
{
    int bh = blockIdx.x;           // 4 blocks
    int t = threadIdx.x;           // 128 threads
    __shared__ float red[128];
    red[t] = g_A[bh * NN + t];
    __syncthreads();
    for (int s = 64; s > 0; s >>= 1) {
        if (t < s) red[t] += red[t + s];
        __syncthreads();
    }
    if (t == 0) g_S0[bh] = red[0];
}

// ---------------------------------------------------------------------------
// Scores via closed form + softmax; write attn to scratch + d_out tail
// ---------------------------------------------------------------------------
__global__ void softmax_kernel(float* __restrict__ attn_out)
{
    int bid = blockIdx.x;          // bh*N + n
    int n = bid & 127;
    int bh = bid >> 7;
    int b = bh >> 1;
    int m = threadIdx.x;           // 128 threads

    float S0 = g_S0[bh];
    float An = g_A[bh * NN + n];
    float s;
    if (m == n) {
        s = S0 - An + g_Dd[b * NN + n];
    } else {
        s = S0 - An - g_A[bh * NN + m] + g_Bq[bh * NN + n] + g_Ck[bh * NN + m];
    }
    s *= SCALE;

    __shared__ float red[128];
    red[m] = s;
    __syncthreads();
    for (int st = 64; st > 0; st >>= 1) {
        if (m < st) red[m] = fmaxf(red[m], red[m + st]);
        __syncthreads();
    }
    float mx = red[0];
    __syncthreads();

    float e = expf(s - mx);
    red[m] = e;
    __syncthreads();
    for (int st = 64; st > 0; st >>= 1) {
        if (m < st) red[m] += red[m + st];
        __syncthreads();
    }
    float a = e / red[0];

    g_attn[(size_t)bid * NN + m] = a;
    attn_out[(size_t)bid * NN + m] = a;
}

// ---------------------------------------------------------------------------
// Final assembly: out[b,i,jp,o] =
//   (1-a0)*Vw[bh,j0,0,o] + a0*Bw[b,j0,0,o] + (1-a1)*Vw[bh,j1,1,o] + a1*Bw[b,j1,1,o] + bo[o]
// where h = jp>>6, j0 = 2*(jp&63), j1 = j0+1, a{0,1} = attn[b,h,i,j{0,1}]
// ---------------------------------------------------------------------------
__global__ void assemble_kernel(const float* __restrict__ bo,
                                float* __restrict__ out)
{
    int bid = blockIdx.x;          // (b*N + i)*N + jp, 32768 blocks
    int jp = bid & 127;
    int bi = bid >> 7;
    int i = bi & 127;
    int b = bi >> 7;
    int h = jp >> 6;
    int jj = jp & 63;
    int j0 = jj * 2;
    int j1 = j0 + 1;
    int bh = b * HH + h;

    float a0 = g_attn[((size_t)(bh * NN) + i) * NN + j0];
    float a1 = g_attn[((size_t)(bh * NN) + i) * NN + j1];

    const float4* vw0 = (const float4*)&g_Vw[(size_t)((bh * NN + j0) * 2 + 0) * DM];
    const float4* vw1 = (const float4*)&g_Vw[(size_t)((bh * NN + j1) * 2 + 1) * DM];
    const float4* bw0 = (const float4*)&g_Bw[(size_t)((b * NN + j0) * 2 + 0) * DM];
    const float4* bw1 = (const float4*)&g_Bw[(size_t)((b * NN + j1) * 2 + 1) * DM];
    const float4* bo4 = (const float4*)bo;
    float4* o4 = (float4*)&out[(size_t)bid * DM];

    int t = threadIdx.x;           // 128 threads, one float4 each
    float4 v0 = vw0[t], v1 = vw1[t], w0 = bw0[t], w1 = bw1[t], bb = bo4[t];
    float c0 = 1.f - a0, c1 = 1.f - a1;
    float4 r;
    r.x = c0 * v0.x + a0 * w0.x + c1 * v1.x + a1 * w1.x + bb.x;
    r.y = c0 * v0.y + a0 * w0.y + c1 * v1.y + a1 * w1.y + bb.y;
    r.z = c0 * v0.z + a0 * w0.z + c1 * v1.z + a1 * w1.z + bb.z;
    r.w = c0 * v0.w + a0 * w0.w + c1 * v1.w + a1 * w1.w + bb.w;
    o4[t] = r;
}

// ---------------------------------------------------------------------------
extern "C" void kernel_launch(void* const* d_in, const int* in_sizes, int n_in,
                              void* d_out, int out_size)
{
    const float* query = (const float*)d_in[0];
    const float* key   = (const float*)d_in[1];
    const float* value = (const float*)d_in[2];
    const float* boxes = (const float*)d_in[3];
    const float* Wq = (const float*)d_in[4];
    const float* bq = (const float*)d_in[5];
    const float* Wk = (const float*)d_in[6];
    const float* bk = (const float*)d_in[7];
    const float* Wv = (const float*)d_in[8];
    const float* bv = (const float*)d_in[9];
    const float* Wbox = (const float*)d_in[10];
    const float* bbox = (const float*)d_in[11];
    const float* Wo = (const float*)d_in[12];
    const float* bo = (const float*)d_in[13];

    float* out = (float*)d_out;
    float* attn_out = out + OUT_ELEMS;

    void *p_q, *p_k, *p_v, *p_bx, *p_Vw, *p_Bw;
    cudaGetSymbolAddress(&p_q,  g_q);
    cudaGetSymbolAddress(&p_k,  g_k);
    cudaGetSymbolAddress(&p_v,  g_v);
    cudaGetSymbolAddress(&p_bx, g_bx);
    cudaGetSymbolAddress(&p_Vw, g_Vw);
    cudaGetSymbolAddress(&p_Bw, g_Bw);

    dim3 blk(256);

    // Projections: q/k/v (256x512 @ 512x512), bx (256x512 @ 512x256)
    gemm_kernel<<<dim3(8, 4), blk>>>(query, Wq, bq, DM, DM, (float*)p_q, 0, 1);
    gemm_kernel<<<dim3(8, 4), blk>>>(key,   Wk, bk, DM, DM, (float*)p_k, 0, 1);
    gemm_kernel<<<dim3(8, 4), blk>>>(value, Wv, bv, DM, DM, (float*)p_v, 0, 1);
    gemm_kernel<<<dim3(4, 4), blk>>>(boxes, Wbox, bbox, DM, DK, (float*)p_bx, DK, 0);

    // Vw = v @ Wo halves, Bw = bx @ Wo halves
    gemm_kernel<<<dim3(8, 8), blk>>>((const float*)p_v, Wo,             nullptr, DK, DM,
                                     (float*)p_Vw,       2 * DM, 0);
    gemm_kernel<<<dim3(8, 8), blk>>>((const float*)p_v, Wo + DK * DM,   nullptr, DK, DM,
                                     (float*)p_Vw + DM,  2 * DM, 0);
    gemm_kernel<<<dim3(8, 4), blk>>>((const float*)p_bx, Wo,            nullptr, DK, DM,
                                     (float*)p_Bw,       2 * DM, 0);
    gemm_kernel<<<dim3(8, 4), blk>>>((const float*)p_bx, Wo + DK * DM,  nullptr, DK, DM,
                                     (float*)p_Bw + DM,  2 * DM, 0);

    // Dot products, S0, softmax
    dots_kernel<<<BHN, 128>>>();
    s0_kernel<<<BB * HH, 128>>>();
    softmax_kernel<<<BB * HH * NN, 128>>>(attn_out);

    // Final assembly: 32768 output rows of 512 floats
    assemble_kernel<<<BB * NN * NN, 128>>>(bo, out);
}

// round 2
// speedup vs baseline: 2.5026x; 2.5026x over previous
#include <cuda_runtime.h>
#include <math.h>

#define BB 2
#define NN 128
#define HH 2
#define DM 512
#define DK 256
#define BHN (BB*HH*NN)                 // 512
#define SCALE 0.005524271728019903f   // 1/sqrt(128*256)
#define OUT_ELEMS (BB*NN*NN*DM)        // 16777216

// Scratch
__device__ float g_q[BHN*DK];
__device__ float g_k[BHN*DK];
__device__ float g_v[BHN*DK];
__device__ float g_bx[BB*NN*DK];
__device__ float g_A[BHN];
__device__ float g_Bq[BHN];
__device__ float g_Ck[BHN];
__device__ float g_Dd[BB*NN];
__device__ float g_Vw[BHN*2*DM];       // [(bh,j)][hp][o]
__device__ float g_Bw[BB*NN*2*DM];     // [(b,j)][hp][o]

// ---------------------------------------------------------------------------
// 64x64 fp32 tile GEMM core: acc += A[row0:+64, :K] @ W[:K, col0:+64]
// 256 threads, 4x4 per thread, k-tile 32, float4 smem reads.
// ---------------------------------------------------------------------------
struct TileSmem {
    float sA[32][68];   // [k][m], pad 4 keeps float4 alignment
    float sB[32][64];   // [k][n]
};

__device__ __forceinline__ void gemm_tile(const float* __restrict__ A,
                                          const float* __restrict__ W,
                                          int K, int wcols, int row0, int col0,
                                          TileSmem& s, float acc[4][4])
{
    int t  = threadIdx.x;
    int tx = t & 15, ty = t >> 4;

    for (int k0 = 0; k0 < K; k0 += 32) {
#pragma unroll
        for (int l = 0; l < 8; ++l) {
            int lin = t + l * 256;
            int kk = lin & 31, r = lin >> 5;
            s.sA[kk][r] = A[(size_t)(row0 + r) * K + k0 + kk];
        }
#pragma unroll
        for (int l = 0; l < 8; ++l) {
            int lin = t + l * 256;
            int c = lin & 63, kk = lin >> 6;
            s.sB[kk][c] = W[(size_t)(k0 + kk) * wcols + col0 + c];
        }
        __syncthreads();
#pragma unroll
        for (int kk = 0; kk < 32; ++kk) {
            float4 av = *(const float4*)&s.sA[kk][ty * 4];
            float4 bv = *(const float4*)&s.sB[kk][tx * 4];
            acc[0][0] += av.x * bv.x; acc[0][1] += av.x * bv.y;
            acc[0][2] += av.x * bv.z; acc[0][3] += av.x * bv.w;
            acc[1][0] += av.y * bv.x; acc[1][1] += av.y * bv.y;
            acc[1][2] += av.y * bv.z; acc[1][3] += av.y * bv.w;
            acc[2][0] += av.z * bv.x; acc[2][1] += av.z * bv.y;
            acc[2][2] += av.z * bv.z; acc[2][3] += av.z * bv.w;
            acc[3][0] += av.w * bv.x; acc[3][1] += av.w * bv.y;
            acc[3][2] += av.w * bv.z; acc[3][3] += av.w * bv.w;
        }
        __syncthreads();
    }
}

// ---------------------------------------------------------------------------
// Stage A: fused q/k/v/bx projections. grid = (28, 4). col tiles:
// [0,8)->q  [8,16)->k  [16,24)->v  [24,28)->bx
// ---------------------------------------------------------------------------
__global__ __launch_bounds__(256) void projA_kernel(
    const float* __restrict__ query, const float* __restrict__ key,
    const float* __restrict__ value, const float* __restrict__ boxes,
    const float* __restrict__ Wq, const float* __restrict__ bq,
    const float* __restrict__ Wk, const float* __restrict__ bk,
    const float* __restrict__ Wv, const float* __restrict__ bv,
    const float* __restrict__ Wbox, const float* __restrict__ bbox)
{
    __shared__ TileSmem s;
    int ct = blockIdx.x;
    int which = ct >> 3;                 // 0..3
    int col0 = (ct - which * 8) * 64;
    int row0 = blockIdx.y * 64;

    const float* A; const float* W; const float* bias; float* out; int wcols;
    if      (which == 0) { A = query; W = Wq;   bias = bq;   out = g_q;  wcols = DM; }
    else if (which == 1) { A = key;   W = Wk;   bias = bk;   out = g_k;  wcols = DM; }
    else if (which == 2) { A = value; W = Wv;   bias = bv;   out = g_v;  wcols = DM; }
    else                 { A = boxes; W = Wbox; bias = bbox; out = g_bx; wcols = DK; }

    float acc[4][4];
#pragma unroll
    for (int i = 0; i < 4; i++)
#pragma unroll
        for (int j = 0; j < 4; j++) acc[i][j] = 0.f;

    gemm_tile(A, W, DM, wcols, row0, col0, s, acc);

    int t = threadIdx.x;
    int tx = t & 15, ty = t >> 4;
#pragma unroll
    for (int i = 0; i < 4; ++i) {
        int row = row0 + ty * 4 + i;
        int b = row >> 7, n = row & 127;
#pragma unroll
        for (int j = 0; j < 4; ++j) {
            int col = col0 + tx * 4 + j;
            float val = acc[i][j] + bias[col];
            if (which < 3) {
                int h = col >> 8, dk = col & 255;
                out[(((b * HH + h) * NN) + n) * DK + dk] = val;
            } else {
                out[row * DK + col] = val;
            }
        }
    }
}

// ---------------------------------------------------------------------------
// Stage B: Vw = v @ Wo halves, Bw = bx @ Wo halves.
// grid = (8, 8, 4): z = src*2 + hp  (src 0=v rows 512, 1=bx rows 256)
// ---------------------------------------------------------------------------
__global__ __launch_bounds__(256) void projB_kernel(const float* __restrict__ Wo)
{
    __shared__ TileSmem s;
    int z = blockIdx.z;
    int src = z >> 1, hp = z & 1;
    int row0 = blockIdx.y * 64;
    if (src == 1 && row0 >= 256) return;
    int col0 = blockIdx.x * 64;

    const float* A = src ? g_bx : g_v;
    float* out = src ? g_Bw : g_Vw;
    const float* W = Wo + (size_t)hp * DK * DM;   // rows [hp*256, +256)

    float acc[4][4];
#pragma unroll
    for (int i = 0; i < 4; i++)
#pragma unroll
        for (int j = 0; j < 4; j++) acc[i][j] = 0.f;

    gemm_tile(A, W, DK, DM, row0, col0, s, acc);

    int t = threadIdx.x;
    int tx = t & 15, ty = t >> 4;
#pragma unroll
    for (int i = 0; i < 4; ++i) {
        int row = row0 + ty * 4 + i;
#pragma unroll
        for (int j = 0; j < 4; ++j) {
            int col = col0 + tx * 4 + j;
            out[(size_t)row * (2 * DM) + hp * DM + col] = acc[i][j];
        }
    }
}

// ---------------------------------------------------------------------------
// Per-(b,h,j) dot products
// ---------------------------------------------------------------------------
__global__ void dots_kernel()
{
    int bid = blockIdx.x;          // bh*N + j
    int j = bid & 127;
    int bh = bid >> 7;
    int b = bh >> 1;
    int t = threadIdx.x;           // 128

    const float* qr = g_q  + (size_t)bid * DK;
    const float* kr = g_k  + (size_t)bid * DK;
    const float* br = g_bx + (size_t)(b * NN + j) * DK;

    float pa = 0.f, pb = 0.f, pc = 0.f, pd = 0.f;
#pragma unroll
    for (int d = t; d < DK; d += 128) {
        float qv = qr[d], kv = kr[d], bvv = br[d];
        pa += qv * kv; pb += bvv * kv; pc += qv * bvv; pd += bvv * bvv;
    }
    __shared__ float red[4][128];
    red[0][t] = pa; red[1][t] = pb; red[2][t] = pc; red[3][t] = pd;
    __syncthreads();
    for (int sst = 64; sst > 0; sst >>= 1) {
        if (t < sst) {
#pragma unroll
            for (int r = 0; r < 4; r++) red[r][t] += red[r][t + sst];
        }
        __syncthreads();
    }
    if (t == 0) {
        g_A[bid]  = red[0][0];
        g_Bq[bid] = red[1][0];
        g_Ck[bid] = red[2][0];
        if ((bh & 1) == 0) g_Dd[b * NN + j] = red[3][0];
    }
}

// ---------------------------------------------------------------------------
// Softmax with fused S0; writes attn straight to d_out tail
// ---------------------------------------------------------------------------
__global__ void softmax_kernel(float* __restrict__ attn_out)
{
    int bid = blockIdx.x;          // bh*N + n
    int n = bid & 127;
    int bh = bid >> 7;
    int b = bh >> 1;
    int m = threadIdx.x;           // 128

    float Am = g_A[bh * NN + m];
    __shared__ float red[128];

    // S0 = sum_m A[bh,m]
    red[m] = Am;
    __syncthreads();
    for (int st = 64; st > 0; st >>= 1) {
        if (m < st) red[m] += red[m + st];
        __syncthreads();
    }
    float S0 = red[0];
    __syncthreads();

    float An = g_A[bh * NN + n];
    float s;
    if (m == n) s = S0 - An + g_Dd[b * NN + n];
    else        s = S0 - An - Am + g_Bq[bh * NN + n] + g_Ck[bh * NN + m];
    s *= SCALE;

    red[m] = s;
    __syncthreads();
    for (int st = 64; st > 0; st >>= 1) {
        if (m < st) red[m] = fmaxf(red[m], red[m + st]);
        __syncthreads();
    }
    float mx = red[0];
    __syncthreads();

    float e = expf(s - mx);
    red[m] = e;
    __syncthreads();
    for (int st = 64; st > 0; st >>= 1) {
        if (m < st) red[m] += red[m + st];
        __syncthreads();
    }
    attn_out[(size_t)bid * NN + m] = e / red[0];
}

// ---------------------------------------------------------------------------
// Assembly: one block per (b, jp). Column vectors base/d0/d1 are i-invariant:
// hoist to registers, loop over 128 i rows — pure streaming write.
// out[b,i,jp,:] = base + a0*d0 + a1*d1
// ---------------------------------------------------------------------------
__global__ __launch_bounds__(256) void assemble_kernel(
    const float* __restrict__ bo, const float* __restrict__ attn,
    float* __restrict__ out)
{
    int bid = blockIdx.x;          // b*128 + jp
    int jp = bid & 127, b = bid >> 7;
    int h = jp >> 6, jj = jp & 63;
    int j0 = 2 * jj, j1 = j0 + 1;
    int bh = b * HH + h;

    __shared__ float sbase[512], sd0[512], sd1[512];
    __shared__ float sa[128][2];

    int t = threadIdx.x;           // 256
    for (int c = t; c < 512; c += 256) {
        float v0 = g_Vw[(size_t)((bh * NN + j0) * 2 + 0) * DM + c];
        float v1 = g_Vw[(size_t)((bh * NN + j1) * 2 + 1) * DM + c];
        float w0 = g_Bw[(size_t)((b  * NN + j0) * 2 + 0) * DM + c];
        float w1 = g_Bw[(size_t)((b  * NN + j1) * 2 + 1) * DM + c];
        sbase[c] = v0 + v1 + bo[c];
        sd0[c]   = w0 - v0;
        sd1[c]   = w1 - v1;
    }
    {
        int i = t >> 1, w = t & 1;
        sa[i][w] = attn[((size_t)(bh * NN) + i) * NN + j0 + w];
    }
    __syncthreads();

    int sub = t >> 7;              // 0/1: which of 2 rows per iter
    int c4 = (t & 127) * 4;
    float4 rb = *(const float4*)&sbase[c4];
    float4 r0 = *(const float4*)&sd0[c4];
    float4 r1 = *(const float4*)&sd1[c4];

#pragma unroll 4
    for (int it = 0; it < 64; ++it) {
        int i = it * 2 + sub;
        float a0 = sa[i][0], a1 = sa[i][1];
        float4 r;
        r.x = rb.x + a0 * r0.x + a1 * r1.x;
        r.y = rb.y + a0 * r0.y + a1 * r1.y;
        r.z = rb.z + a0 * r0.z + a1 * r1.z;
        r.w = rb.w + a0 * r0.w + a1 * r1.w;
        *(float4*)&out[(((size_t)(b * NN + i) * NN) + jp) * DM + c4] = r;
    }
}

// ---------------------------------------------------------------------------
extern "C" void kernel_launch(void* const* d_in, const int* in_sizes, int n_in,
                              void* d_out, int out_size)
{
    const float* query = (const float*)d_in[0];
    const float* key   = (const float*)d_in[1];
    const float* value = (const float*)d_in[2];
    const float* boxes = (const float*)d_in[3];
    const float* Wq = (const float*)d_in[4];
    const float* bq = (const float*)d_in[5];
    const float* Wk = (const float*)d_in[6];
    const float* bk = (const float*)d_in[7];
    const float* Wv = (const float*)d_in[8];
    const float* bv = (const float*)d_in[9];
    const float* Wbox = (const float*)d_in[10];
    const float* bbox = (const float*)d_in[11];
    const float* Wo = (const float*)d_in[12];
    const float* bo = (const float*)d_in[13];

    float* out = (float*)d_out;
    float* attn_out = out + OUT_ELEMS;

    projA_kernel<<<dim3(28, 4), 256>>>(query, key, value, boxes,
                                       Wq, bq, Wk, bk, Wv, bv, Wbox, bbox);
    dots_kernel<<<BHN, 128>>>();
    softmax_kernel<<<BB * HH * NN, 128>>>(attn_out);
    projB_kernel<<<dim3(8, 8, 4), 256>>>(Wo);
    assemble_kernel<<<BB * NN, 256>>>(bo, attn_out, out);
}

// round 3
// speedup vs baseline: 3.3952x; 1.3567x over previous
#include <cuda_runtime.h>
#include <math.h>

#define BB 2
#define NN 128
#define HH 2
#define DM 512
#define DK 256
#define BHN (BB*NN*HH)                 // 512
#define SCALE 0.005524271728019903f   // 1/sqrt(128*256)
#define OUT_ELEMS (BB*NN*NN*DM)        // 16777216

__device__ float g_q[BHN*DK];
__device__ float g_k[BHN*DK];
__device__ float g_v[BHN*DK];
__device__ float g_bx[BB*NN*DK];
__device__ float g_A[BHN];
__device__ float g_Bq[BHN];
__device__ float g_Ck[BHN];
__device__ float g_Dd[BB*NN];
__device__ float g_Vw[BHN*2*DM];       // [(bh,j)][hp][o]
__device__ float g_Bw[BB*NN*2*DM];     // [(b,j)][hp][o]

// ---------------------------------------------------------------------------
// 64x64 fp32 tile GEMM core, double-buffered, float4 global loads.
// 256 threads, 4x4 per thread, k-tile 32.
// ---------------------------------------------------------------------------
struct TileSmem {
    float sA[2][32][68];   // [buf][k][m] (pad to 68 keeps 16B align for float4 reads)
    float sB[2][32][64];   // [buf][k][n]
};

__device__ __forceinline__ void gemm_tile(const float* __restrict__ A,
                                          const float* __restrict__ W,
                                          int K, int wcols, int row0, int col0,
                                          TileSmem& s, float acc[4][4])
{
    const int t  = threadIdx.x;
    const int tx = t & 15, ty = t >> 4;

    // A-load mapping: lin = t + 256*l (l=0,1); kq = lin & 7, r = lin >> 3
    const int a_kq = t & 7;
    const int a_r0 = t >> 3;            // rows 0..31 (l=0), 32..63 (l=1)
    // B-load mapping: c4 = (lin & 15)*4, kk = lin >> 4
    const int b_c = (t & 15) * 4;
    const int b_k0 = t >> 4;            // 0..15 (l=0), +16 (l=1)

    const int nk = K >> 5;
    float4 ra[2], rb[2];

    // prologue: load tile 0
#pragma unroll
    for (int l = 0; l < 2; ++l) {
        ra[l] = *(const float4*)&A[(size_t)(row0 + a_r0 + l * 32) * K + a_kq * 4];
        rb[l] = *(const float4*)&W[(size_t)(b_k0 + l * 16) * wcols + col0 + b_c];
    }
#pragma unroll
    for (int l = 0; l < 2; ++l) {
        int r = a_r0 + l * 32, kq = a_kq * 4;
        s.sA[0][kq + 0][r] = ra[l].x;
        s.sA[0][kq + 1][r] = ra[l].y;
        s.sA[0][kq + 2][r] = ra[l].z;
        s.sA[0][kq + 3][r] = ra[l].w;
        *(float4*)&s.sB[0][b_k0 + l * 16][b_c] = rb[l];
    }
    __syncthreads();

    for (int kt = 0; kt < nk; ++kt) {
        int cur = kt & 1, nxt = cur ^ 1;
        if (kt + 1 < nk) {
            int k0 = (kt + 1) * 32;
#pragma unroll
            for (int l = 0; l < 2; ++l) {
                ra[l] = *(const float4*)&A[(size_t)(row0 + a_r0 + l * 32) * K + k0 + a_kq * 4];
                rb[l] = *(const float4*)&W[(size_t)(k0 + b_k0 + l * 16) * wcols + col0 + b_c];
            }
        }
#pragma unroll
        for (int kk = 0; kk < 32; ++kk) {
            float4 av = *(const float4*)&s.sA[cur][kk][ty * 4];
            float4 bv = *(const float4*)&s.sB[cur][kk][tx * 4];
            acc[0][0] += av.x * bv.x; acc[0][1] += av.x * bv.y;
            acc[0][2] += av.x * bv.z; acc[0][3] += av.x * bv.w;
            acc[1][0] += av.y * bv.x; acc[1][1] += av.y * bv.y;
            acc[1][2] += av.y * bv.z; acc[1][3] += av.y * bv.w;
            acc[2][0] += av.z * bv.x; acc[2][1] += av.z * bv.y;
            acc[2][2] += av.z * bv.z; acc[2][3] += av.z * bv.w;
            acc[3][0] += av.w * bv.x; acc[3][1] += av.w * bv.y;
            acc[3][2] += av.w * bv.z; acc[3][3] += av.w * bv.w;
        }
        if (kt + 1 < nk) {
#pragma unroll
            for (int l = 0; l < 2; ++l) {
                int r = a_r0 + l * 32, kq = a_kq * 4;
                s.sA[nxt][kq + 0][r] = ra[l].x;
                s.sA[nxt][kq + 1][r] = ra[l].y;
                s.sA[nxt][kq + 2][r] = ra[l].z;
                s.sA[nxt][kq + 3][r] = ra[l].w;
                *(float4*)&s.sB[nxt][b_k0 + l * 16][b_c] = rb[l];
            }
        }
        __syncthreads();
    }
}

// ---------------------------------------------------------------------------
// Stage A: fused q/k/v/bx projections. grid = (28, 4).
// ---------------------------------------------------------------------------
__global__ __launch_bounds__(256) void projA_kernel(
    const float* __restrict__ query, const float* __restrict__ key,
    const float* __restrict__ value, const float* __restrict__ boxes,
    const float* __restrict__ Wq, const float* __restrict__ bq,
    const float* __restrict__ Wk, const float* __restrict__ bk,
    const float* __restrict__ Wv, const float* __restrict__ bv,
    const float* __restrict__ Wbox, const float* __restrict__ bbox)
{
    __shared__ TileSmem s;
    int ct = blockIdx.x;
    int which = ct >> 3;
    int col0 = (ct - which * 8) * 64;
    int row0 = blockIdx.y * 64;

    const float* A; const float* W; const float* bias; float* out; int wcols;
    if      (which == 0) { A = query; W = Wq;   bias = bq;   out = g_q;  wcols = DM; }
    else if (which == 1) { A = key;   W = Wk;   bias = bk;   out = g_k;  wcols = DM; }
    else if (which == 2) { A = value; W = Wv;   bias = bv;   out = g_v;  wcols = DM; }
    else                 { A = boxes; W = Wbox; bias = bbox; out = g_bx; wcols = DK; }

    float acc[4][4];
#pragma unroll
    for (int i = 0; i < 4; i++)
#pragma unroll
        for (int j = 0; j < 4; j++) acc[i][j] = 0.f;

    gemm_tile(A, W, DM, wcols, row0, col0, s, acc);

    int t = threadIdx.x;
    int tx = t & 15, ty = t >> 4;
#pragma unroll
    for (int i = 0; i < 4; ++i) {
        int row = row0 + ty * 4 + i;
        int b = row >> 7, n = row & 127;
#pragma unroll
        for (int j = 0; j < 4; ++j) {
            int col = col0 + tx * 4 + j;
            float val = acc[i][j] + bias[col];
            if (which < 3) {
                int h = col >> 8, dk = col & 255;
                out[(((b * HH + h) * NN) + n) * DK + dk] = val;
            } else {
                out[row * DK + col] = val;
            }
        }
    }
}

// ---------------------------------------------------------------------------
// Stage B: Vw = v @ Wo_half, Bw = bx @ Wo_half.
// grid.x = 8 (col tiles), grid.y = 24: y<16 -> Vw (src rows 512, 8 y per hp... )
// Encode: blocks 0..15 -> Vw hp=(y>>3), rowtile=y&7 ; 16..23 -> Bw hp=((y-16)>>2), rowtile=(y-16)&3
// ---------------------------------------------------------------------------
__global__ __launch_bounds__(256) void projB_kernel(const float* __restrict__ Wo)
{
    __shared__ TileSmem s;
    int y = blockIdx.y;
    const float* A; float* out; int row0, hp;
    if (y < 16) { A = g_v;  out = g_Vw; hp = y >> 3; row0 = (y & 7) * 64; }
    else        { y -= 16; A = g_bx; out = g_Bw; hp = y >> 2; row0 = (y & 3) * 64; }
    int col0 = blockIdx.x * 64;
    const float* W = Wo + (size_t)hp * DK * DM;

    float acc[4][4];
#pragma unroll
    for (int i = 0; i < 4; i++)
#pragma unroll
        for (int j = 0; j < 4; j++) acc[i][j] = 0.f;

    gemm_tile(A, W, DK, DM, row0, col0, s, acc);

    int t = threadIdx.x;
    int tx = t & 15, ty = t >> 4;
#pragma unroll
    for (int i = 0; i < 4; ++i) {
        int row = row0 + ty * 4 + i;
#pragma unroll
        for (int j = 0; j < 4; ++j) {
            int col = col0 + tx * 4 + j;
            out[(size_t)row * (2 * DM) + hp * DM + col] = acc[i][j];
        }
    }
}

// ---------------------------------------------------------------------------
// Dot products: warp per j, float4 loads, shuffle reduce. grid=128, 128 thr.
// ---------------------------------------------------------------------------
__global__ void dots_kernel()
{
    int w = threadIdx.x >> 5;
    int lane = threadIdx.x & 31;
    int bid = blockIdx.x * 4 + w;   // bh*N + j
    int j = bid & 127;
    int bh = bid >> 7;
    int b = bh >> 1;

    const float4* qr = (const float4*)(g_q  + (size_t)bid * DK);
    const float4* kr = (const float4*)(g_k  + (size_t)bid * DK);
    const float4* br = (const float4*)(g_bx + (size_t)(b * NN + j) * DK);

    float pa = 0.f, pb = 0.f, pc = 0.f, pd = 0.f;
#pragma unroll
    for (int d = lane; d < 64; d += 32) {
        float4 qv = qr[d], kv = kr[d], bv = br[d];
        pa += qv.x*kv.x + qv.y*kv.y + qv.z*kv.z + qv.w*kv.w;
        pb += bv.x*kv.x + bv.y*kv.y + bv.z*kv.z + bv.w*kv.w;
        pc += qv.x*bv.x + qv.y*bv.y + qv.z*bv.z + qv.w*bv.w;
        pd += bv.x*bv.x + bv.y*bv.y + bv.z*bv.z + bv.w*bv.w;
    }
#pragma unroll
    for (int off = 16; off > 0; off >>= 1) {
        pa += __shfl_down_sync(0xffffffff, pa, off);
        pb += __shfl_down_sync(0xffffffff, pb, off);
        pc += __shfl_down_sync(0xffffffff, pc, off);
        pd += __shfl_down_sync(0xffffffff, pd, off);
    }
    if (lane == 0) {
        g_A[bid] = pa;
        g_Bq[bid] = pb;
        g_Ck[bid] = pc;
        if ((bh & 1) == 0) g_Dd[b * NN + j] = pd;
    }
}

// ---------------------------------------------------------------------------
// Softmax with fused S0; writes attn straight to d_out tail
// ---------------------------------------------------------------------------
__global__ void softmax_kernel(float* __restrict__ attn_out)
{
    int bid = blockIdx.x;          // bh*N + n
    int n = bid & 127;
    int bh = bid >> 7;
    int b = bh >> 1;
    int m = threadIdx.x;           // 128

    float Am = g_A[bh * NN + m];
    __shared__ float red[128];

    red[m] = Am;
    __syncthreads();
    for (int st = 64; st > 0; st >>= 1) {
        if (m < st) red[m] += red[m + st];
        __syncthreads();
    }
    float S0 = red[0];
    __syncthreads();

    float An = g_A[bh * NN + n];
    float sv;
    if (m == n) sv = S0 - An + g_Dd[b * NN + n];
    else        sv = S0 - An - Am + g_Bq[bh * NN + n] + g_Ck[bh * NN + m];
    sv *= SCALE;

    red[m] = sv;
    __syncthreads();
    for (int st = 64; st > 0; st >>= 1) {
        if (m < st) red[m] = fmaxf(red[m], red[m + st]);
        __syncthreads();
    }
    float mx = red[0];
    __syncthreads();

    float e = expf(sv - mx);
    red[m] = e;
    __syncthreads();
    for (int st = 64; st > 0; st >>= 1) {
        if (m < st) red[m] += red[m + st];
        __syncthreads();
    }
    attn_out[(size_t)bid * NN + m] = e / red[0];
}

// ---------------------------------------------------------------------------
// Assembly: block per (b, jp, ihalf). out[b,i,jp,:] = base + a0*d0 + a1*d1
// ---------------------------------------------------------------------------
__global__ __launch_bounds__(256) void assemble_kernel(
    const float* __restrict__ bo, const float* __restrict__ attn,
    float* __restrict__ out)
{
    int bid = blockIdx.x;          // (b*128 + jp)*2 + ihalf
    int ihalf = bid & 1;
    int bjp = bid >> 1;
    int jp = bjp & 127, b = bjp >> 7;
    int h = jp >> 6, jj = jp & 63;
    int j0 = 2 * jj, j1 = j0 + 1;
    int bh = b * HH + h;

    __shared__ float sbase[512], sd0[512], sd1[512];
    __shared__ float sa[64][2];

    int t = threadIdx.x;           // 256
    for (int c = t; c < 512; c += 256) {
        float v0 = g_Vw[(size_t)((bh * NN + j0) * 2 + 0) * DM + c];
        float v1 = g_Vw[(size_t)((bh * NN + j1) * 2 + 1) * DM + c];
        float w0 = g_Bw[(size_t)((b  * NN + j0) * 2 + 0) * DM + c];
        float w1 = g_Bw[(size_t)((b  * NN + j1) * 2 + 1) * DM + c];
        sbase[c] = v0 + v1 + bo[c];
        sd0[c]   = w0 - v0;
        sd1[c]   = w1 - v1;
    }
    if (t < 128) {
        int i = ihalf * 64 + (t >> 1), w = t & 1;
        sa[t >> 1][w] = attn[((size_t)(bh * NN) + i) * NN + j0 + w];
    }
    __syncthreads();

    int sub = t >> 7;              // 0/1
    int c4 = (t & 127) * 4;
    float4 rb = *(const float4*)&sbase[c4];
    float4 r0 = *(const float4*)&sd0[c4];
    float4 r1 = *(const float4*)&sd1[c4];

#pragma unroll 4
    for (int it = 0; it < 32; ++it) {
        int il = it * 2 + sub;
        int i = ihalf * 64 + il;
        float a0 = sa[il][0], a1 = sa[il][1];
        float4 r;
        r.x = rb.x + a0 * r0.x + a1 * r1.x;
        r.y = rb.y + a0 * r0.y + a1 * r1.y;
        r.z = rb.z + a0 * r0.z + a1 * r1.z;
        r.w = rb.w + a0 * r0.w + a1 * r1.w;
        *(float4*)&out[(((size_t)(b * NN + i) * NN) + jp) * DM + c4] = r;
    }
}

// ---------------------------------------------------------------------------
extern "C" void kernel_launch(void* const* d_in, const int* in_sizes, int n_in,
                              void* d_out, int out_size)
{
    const float* query = (const float*)d_in[0];
    const float* key   = (const float*)d_in[1];
    const float* value = (const float*)d_in[2];
    const float* boxes = (const float*)d_in[3];
    const float* Wq = (const float*)d_in[4];
    const float* bq = (const float*)d_in[5];
    const float* Wk = (const float*)d_in[6];
    const float* bk = (const float*)d_in[7];
    const float* Wv = (const float*)d_in[8];
    const float* bv = (const float*)d_in[9];
    const float* Wbox = (const float*)d_in[10];
    const float* bbox = (const float*)d_in[11];
    const float* Wo = (const float*)d_in[12];
    const float* bo = (const float*)d_in[13];

    float* out = (float*)d_out;
    float* attn_out = out + OUT_ELEMS;

    projA_kernel<<<dim3(28, 4), 256>>>(query, key, value, boxes,
                                       Wq, bq, Wk, bk, Wv, bv, Wbox, bbox);
    projB_kernel<<<dim3(8, 24), 256>>>(Wo);
    dots_kernel<<<128, 128>>>();
    softmax_kernel<<<BB * HH * NN, 128>>>(attn_out);
    assemble_kernel<<<BB * NN * 2, 256>>>(bo, attn_out, out);
}

// round 4
// speedup vs baseline: 3.6255x; 1.0678x over previous
#include <cuda_runtime.h>
#include <math.h>
#include <stdint.h>

#define BB 2
#define NN 128
#define HH 2
#define DM 512
#define DK 256
#define BHN 512
#define SCALE 0.005524271728019903f   // 1/sqrt(128*256)
#define OUT_ELEMS (BB*NN*NN*DM)        // 16777216

__device__ float g_q[BHN*DK];
__device__ float g_k[BHN*DK];
__device__ float g_v[BHN*DK];
__device__ float g_bx[BB*NN*DK];
__device__ float g_Vw[BHN*2*DM];       // [(bh,j)][hp][o]
__device__ float g_Bw[BB*NN*2*DM];     // [(b,j)][hp][o]

__device__ __forceinline__ float to_tf32(float x) {
    float r; asm("cvt.rna.tf32.f32 %0, %1;" : "=f"(r) : "f"(x)); return r;
}
__device__ __forceinline__ void mma_tf32(float* c,
        uint32_t a0, uint32_t a1, uint32_t a2, uint32_t a3,
        uint32_t b0, uint32_t b1) {
    asm volatile("mma.sync.aligned.m16n8k8.row.col.f32.tf32.tf32.f32 "
        "{%0,%1,%2,%3},{%4,%5,%6,%7},{%8,%9},{%0,%1,%2,%3};"
        : "+f"(c[0]), "+f"(c[1]), "+f"(c[2]), "+f"(c[3])
        : "r"(a0), "r"(a1), "r"(a2), "r"(a3), "r"(b0), "r"(b1));
}

// ---------------------------------------------------------------------------
// tf32 64x64 block GEMM core. 128 threads (4 warps, 2x2), warp tile 32x32.
// k-tile 16, double-buffered smem, float4 global loads, tf32 cvt on store.
// Smem strides 72 -> conflict-free fragment LDS.
// ---------------------------------------------------------------------------
struct TCSmem {
    float sA[2][16][72];   // [buf][k][m]
    float sB[2][16][72];   // [buf][k][n]
};

template<int K>
__device__ __forceinline__ void gemm_tile_tc(const float* __restrict__ A,
        const float* __restrict__ W, int wcols, int row0, int col0,
        TCSmem& s, float cacc[2][4][4])
{
    const int t = threadIdx.x;
    const int lane = t & 31, warp = t >> 5;
    const int wm = (warp & 1) * 32, wn = (warp >> 1) * 32;
    const int gid = lane >> 2, tig = lane & 3;
    const int a_r = t >> 2, a_q = t & 3;     // A: row a_r+32l, k quad a_q
    const int b_k = t >> 4, b_q = t & 15;    // B: k row b_k+8l, n quad b_q
    constexpr int NK = K / 16;

    float4 ra[2], rb[2];
#pragma unroll
    for (int l = 0; l < 2; ++l) {
        ra[l] = *(const float4*)&A[(size_t)(row0 + a_r + 32 * l) * K + a_q * 4];
        rb[l] = *(const float4*)&W[(size_t)(b_k + 8 * l) * wcols + col0 + b_q * 4];
    }
#pragma unroll
    for (int l = 0; l < 2; ++l) {
        int r = a_r + 32 * l, kq = a_q * 4;
        s.sA[0][kq + 0][r] = to_tf32(ra[l].x);
        s.sA[0][kq + 1][r] = to_tf32(ra[l].y);
        s.sA[0][kq + 2][r] = to_tf32(ra[l].z);
        s.sA[0][kq + 3][r] = to_tf32(ra[l].w);
        int kk = b_k + 8 * l, nq = b_q * 4;
        s.sB[0][kk][nq + 0] = to_tf32(rb[l].x);
        s.sB[0][kk][nq + 1] = to_tf32(rb[l].y);
        s.sB[0][kk][nq + 2] = to_tf32(rb[l].z);
        s.sB[0][kk][nq + 3] = to_tf32(rb[l].w);
    }
    __syncthreads();

#pragma unroll
    for (int kt = 0; kt < NK; ++kt) {
        const int cur = kt & 1, nxt = cur ^ 1;
        if (kt + 1 < NK) {
            int k0 = (kt + 1) * 16;
#pragma unroll
            for (int l = 0; l < 2; ++l) {
                ra[l] = *(const float4*)&A[(size_t)(row0 + a_r + 32 * l) * K + k0 + a_q * 4];
                rb[l] = *(const float4*)&W[(size_t)(k0 + b_k + 8 * l) * wcols + col0 + b_q * 4];
            }
        }
#pragma unroll
        for (int kf = 0; kf < 16; kf += 8) {
            uint32_t af[2][4], bf[4][2];
#pragma unroll
            for (int mi = 0; mi < 2; ++mi) {
                int m0 = wm + mi * 16 + gid;
                af[mi][0] = __float_as_uint(s.sA[cur][kf + tig][m0]);
                af[mi][1] = __float_as_uint(s.sA[cur][kf + tig][m0 + 8]);
                af[mi][2] = __float_as_uint(s.sA[cur][kf + tig + 4][m0]);
                af[mi][3] = __float_as_uint(s.sA[cur][kf + tig + 4][m0 + 8]);
            }
#pragma unroll
            for (int ni = 0; ni < 4; ++ni) {
                int n0 = wn + ni * 8 + gid;
                bf[ni][0] = __float_as_uint(s.sB[cur][kf + tig][n0]);
                bf[ni][1] = __float_as_uint(s.sB[cur][kf + tig + 4][n0]);
            }
#pragma unroll
            for (int mi = 0; mi < 2; ++mi)
#pragma unroll
                for (int ni = 0; ni < 4; ++ni)
                    mma_tf32(cacc[mi][ni], af[mi][0], af[mi][1], af[mi][2], af[mi][3],
                             bf[ni][0], bf[ni][1]);
        }
        if (kt + 1 < NK) {
#pragma unroll
            for (int l = 0; l < 2; ++l) {
                int r = a_r + 32 * l, kq = a_q * 4;
                s.sA[nxt][kq + 0][r] = to_tf32(ra[l].x);
                s.sA[nxt][kq + 1][r] = to_tf32(ra[l].y);
                s.sA[nxt][kq + 2][r] = to_tf32(ra[l].z);
                s.sA[nxt][kq + 3][r] = to_tf32(ra[l].w);
                int kk = b_k + 8 * l, nq = b_q * 4;
                s.sB[nxt][kk][nq + 0] = to_tf32(rb[l].x);
                s.sB[nxt][kk][nq + 1] = to_tf32(rb[l].y);
                s.sB[nxt][kk][nq + 2] = to_tf32(rb[l].z);
                s.sB[nxt][kk][nq + 3] = to_tf32(rb[l].w);
            }
        }
        __syncthreads();
    }
}

// ---------------------------------------------------------------------------
// Stage A: fused q/k/v/bx projections. grid=(28,4), 128 threads.
// ---------------------------------------------------------------------------
__global__ __launch_bounds__(128) void projA_kernel(
    const float* __restrict__ query, const float* __restrict__ key,
    const float* __restrict__ value, const float* __restrict__ boxes,
    const float* __restrict__ Wq, const float* __restrict__ bq,
    const float* __restrict__ Wk, const float* __restrict__ bk,
    const float* __restrict__ Wv, const float* __restrict__ bv,
    const float* __restrict__ Wbox, const float* __restrict__ bbox)
{
    __shared__ TCSmem s;
    int ct = blockIdx.x;
    int which = ct >> 3;
    int col0 = (ct - which * 8) * 64;
    int row0 = blockIdx.y * 64;

    const float* A; const float* W; const float* bias; float* out; int wcols;
    if      (which == 0) { A = query; W = Wq;   bias = bq;   out = g_q;  wcols = DM; }
    else if (which == 1) { A = key;   W = Wk;   bias = bk;   out = g_k;  wcols = DM; }
    else if (which == 2) { A = value; W = Wv;   bias = bv;   out = g_v;  wcols = DM; }
    else                 { A = boxes; W = Wbox; bias = bbox; out = g_bx; wcols = DK; }

    float cacc[2][4][4];
#pragma unroll
    for (int mi = 0; mi < 2; ++mi)
#pragma unroll
        for (int ni = 0; ni < 4; ++ni)
#pragma unroll
            for (int r = 0; r < 4; ++r) cacc[mi][ni][r] = 0.f;

    gemm_tile_tc<DM>(A, W, wcols, row0, col0, s, cacc);

    const int lane = threadIdx.x & 31, warp = threadIdx.x >> 5;
    const int wm = (warp & 1) * 32, wn = (warp >> 1) * 32;
    const int gid = lane >> 2, tig = lane & 3;
#pragma unroll
    for (int mi = 0; mi < 2; ++mi)
#pragma unroll
        for (int rr = 0; rr < 2; ++rr) {
            int row = row0 + wm + mi * 16 + rr * 8 + gid;
            int b = row >> 7, n = row & 127;
#pragma unroll
            for (int ni = 0; ni < 4; ++ni) {
                int col = col0 + wn + ni * 8 + tig * 2;
                float2 v;
                v.x = cacc[mi][ni][rr * 2 + 0] + bias[col];
                v.y = cacc[mi][ni][rr * 2 + 1] + bias[col + 1];
                if (which < 3) {
                    int h = col >> 8, dk = col & 255;
                    *(float2*)&out[(((b * HH + h) * NN) + n) * DK + dk] = v;
                } else {
                    *(float2*)&out[row * DK + col] = v;
                }
            }
        }
}

// ---------------------------------------------------------------------------
// Stage B: Vw = v @ Wo_half, Bw = bx @ Wo_half. grid=(8,24), 128 threads.
// ---------------------------------------------------------------------------
__global__ __launch_bounds__(128) void projB_kernel(const float* __restrict__ Wo)
{
    __shared__ TCSmem s;
    int y = blockIdx.y;
    const float* A; float* out; int row0, hp;
    if (y < 16) { A = g_v;  out = g_Vw; hp = y >> 3; row0 = (y & 7) * 64; }
    else        { y -= 16; A = g_bx; out = g_Bw; hp = y >> 2; row0 = (y & 3) * 64; }
    int col0 = blockIdx.x * 64;
    const float* W = Wo + (size_t)hp * DK * DM;

    float cacc[2][4][4];
#pragma unroll
    for (int mi = 0; mi < 2; ++mi)
#pragma unroll
        for (int ni = 0; ni < 4; ++ni)
#pragma unroll
            for (int r = 0; r < 4; ++r) cacc[mi][ni][r] = 0.f;

    gemm_tile_tc<DK>(A, W, DM, row0, col0, s, cacc);

    const int lane = threadIdx.x & 31, warp = threadIdx.x >> 5;
    const int wm = (warp & 1) * 32, wn = (warp >> 1) * 32;
    const int gid = lane >> 2, tig = lane & 3;
#pragma unroll
    for (int mi = 0; mi < 2; ++mi)
#pragma unroll
        for (int rr = 0; rr < 2; ++rr) {
            int row = row0 + wm + mi * 16 + rr * 8 + gid;
#pragma unroll
            for (int ni = 0; ni < 4; ++ni) {
                int col = col0 + wn + ni * 8 + tig * 2;
                float2 v;
                v.x = cacc[mi][ni][rr * 2 + 0];
                v.y = cacc[mi][ni][rr * 2 + 1];
                *(float2*)&out[(size_t)row * (2 * DM) + hp * DM + col] = v;
            }
        }
}

// ---------------------------------------------------------------------------
// Fused dots + S0 + softmax. grid=4 (bh), 512 threads.
// ---------------------------------------------------------------------------
__global__ __launch_bounds__(512) void attn_kernel(float* __restrict__ attn_out)
{
    int bh = blockIdx.x;
    int b = bh >> 1;
    int t = threadIdx.x;
    int warp = t >> 5, lane = t & 31;

    __shared__ float sA[128], sBq[128], sCk[128], sDd[128];
    __shared__ float part[16];
    __shared__ float sS0;

    // Phase 1: dots, warp per j
#pragma unroll
    for (int r = 0; r < 8; ++r) {
        int j = r * 16 + warp;
        const float4* qr = (const float4*)(g_q  + (size_t)(bh * NN + j) * DK);
        const float4* kr = (const float4*)(g_k  + (size_t)(bh * NN + j) * DK);
        const float4* br = (const float4*)(g_bx + (size_t)(b  * NN + j) * DK);
        float pa = 0.f, pb = 0.f, pc = 0.f, pd = 0.f;
#pragma unroll
        for (int u = 0; u < 2; ++u) {
            int d = lane + u * 32;
            float4 qv = qr[d], kv = kr[d], bv = br[d];
            pa += qv.x*kv.x + qv.y*kv.y + qv.z*kv.z + qv.w*kv.w;
            pb += bv.x*kv.x + bv.y*kv.y + bv.z*kv.z + bv.w*kv.w;
            pc += qv.x*bv.x + qv.y*bv.y + qv.z*bv.z + qv.w*bv.w;
            pd += bv.x*bv.x + bv.y*bv.y + bv.z*bv.z + bv.w*bv.w;
        }
#pragma unroll
        for (int off = 16; off > 0; off >>= 1) {
            pa += __shfl_down_sync(0xffffffff, pa, off);
            pb += __shfl_down_sync(0xffffffff, pb, off);
            pc += __shfl_down_sync(0xffffffff, pc, off);
            pd += __shfl_down_sync(0xffffffff, pd, off);
        }
        if (lane == 0) { sA[j] = pa; sBq[j] = pb; sCk[j] = pc; sDd[j] = pd; }
    }
    __syncthreads();

    // S0 = sum of sA
    if (t < 128) {
        float v = sA[t];
#pragma unroll
        for (int off = 16; off > 0; off >>= 1)
            v += __shfl_down_sync(0xffffffff, v, off);
        if (lane == 0) part[warp] = v;
    }
    __syncthreads();
    if (t == 0) sS0 = part[0] + part[1] + part[2] + part[3];
    __syncthreads();
    float S0 = sS0;

    // Phase 2: softmax, warp per row n
#pragma unroll
    for (int r = 0; r < 8; ++r) {
        int n = r * 16 + warp;
        float An = sA[n], Bqn = sBq[n], Ddn = sDd[n];
        float sv[4];
        float mx = -1e30f;
#pragma unroll
        for (int u = 0; u < 4; ++u) {
            int m = lane + u * 32;
            float x = (m == n) ? (S0 - An + Ddn)
                               : (S0 - An - sA[m] + Bqn + sCk[m]);
            sv[u] = x * SCALE;
            mx = fmaxf(mx, sv[u]);
        }
#pragma unroll
        for (int off = 16; off > 0; off >>= 1)
            mx = fmaxf(mx, __shfl_xor_sync(0xffffffff, mx, off));
        float e[4], tot = 0.f;
#pragma unroll
        for (int u = 0; u < 4; ++u) { e[u] = expf(sv[u] - mx); tot += e[u]; }
#pragma unroll
        for (int off = 16; off > 0; off >>= 1)
            tot += __shfl_xor_sync(0xffffffff, tot, off);
        float inv = 1.f / tot;
        size_t base = ((size_t)(bh * NN) + n) * NN;
#pragma unroll
        for (int u = 0; u < 4; ++u)
            attn_out[base + lane + u * 32] = e[u] * inv;
    }
}

// ---------------------------------------------------------------------------
// Assembly: block per (b, jp, ihalf). out[b,i,jp,:] = base + a0*d0 + a1*d1
// ---------------------------------------------------------------------------
__global__ __launch_bounds__(256) void assemble_kernel(
    const float* __restrict__ bo, const float* __restrict__ attn,
    float* __restrict__ out)
{
    int bid = blockIdx.x;
    int ihalf = bid & 1;
    int bjp = bid >> 1;
    int jp = bjp & 127, b = bjp >> 7;
    int h = jp >> 6, jj = jp & 63;
    int j0 = 2 * jj, j1 = j0 + 1;
    int bh = b * HH + h;

    __shared__ float sbase[512], sd0[512], sd1[512];
    __shared__ float sa[64][2];

    int t = threadIdx.x;
    for (int c = t; c < 512; c += 256) {
        float v0 = g_Vw[(size_t)((bh * NN + j0) * 2 + 0) * DM + c];
        float v1 = g_Vw[(size_t)((bh * NN + j1) * 2 + 1) * DM + c];
        float w0 = g_Bw[(size_t)((b  * NN + j0) * 2 + 0) * DM + c];
        float w1 = g_Bw[(size_t)((b  * NN + j1) * 2 + 1) * DM + c];
        sbase[c] = v0 + v1 + bo[c];
        sd0[c]   = w0 - v0;
        sd1[c]   = w1 - v1;
    }
    if (t < 128) {
        int i = ihalf * 64 + (t >> 1), w = t & 1;
        sa[t >> 1][w] = attn[((size_t)(bh * NN) + i) * NN + j0 + w];
    }
    __syncthreads();

    int sub = t >> 7;
    int c4 = (t & 127) * 4;
    float4 rb = *(const float4*)&sbase[c4];
    float4 r0 = *(const float4*)&sd0[c4];
    float4 r1 = *(const float4*)&sd1[c4];

#pragma unroll 4
    for (int it = 0; it < 32; ++it) {
        int il = it * 2 + sub;
        int i = ihalf * 64 + il;
        float a0 = sa[il][0], a1 = sa[il][1];
        float4 r;
        r.x = rb.x + a0 * r0.x + a1 * r1.x;
        r.y = rb.y + a0 * r0.y + a1 * r1.y;
        r.z = rb.z + a0 * r0.z + a1 * r1.z;
        r.w = rb.w + a0 * r0.w + a1 * r1.w;
        *(float4*)&out[(((size_t)(b * NN + i) * NN) + jp) * DM + c4] = r;
    }
}

// ---------------------------------------------------------------------------
extern "C" void kernel_launch(void* const* d_in, const int* in_sizes, int n_in,
                              void* d_out, int out_size)
{
    const float* query = (const float*)d_in[0];
    const float* key   = (const float*)d_in[1];
    const float* value = (const float*)d_in[2];
    const float* boxes = (const float*)d_in[3];
    const float* Wq = (const float*)d_in[4];
    const float* bq = (const float*)d_in[5];
    const float* Wk = (const float*)d_in[6];
    const float* bk = (const float*)d_in[7];
    const float* Wv = (const float*)d_in[8];
    const float* bv = (const float*)d_in[9];
    const float* Wbox = (const float*)d_in[10];
    const float* bbox = (const float*)d_in[11];
    const float* Wo = (const float*)d_in[12];
    const float* bo = (const float*)d_in[13];

    float* out = (float*)d_out;
    float* attn_out = out + OUT_ELEMS;

    projA_kernel<<<dim3(28, 4), 128>>>(query, key, value, boxes,
                                       Wq, bq, Wk, bk, Wv, bv, Wbox, bbox);
    attn_kernel<<<4, 512>>>(attn_out);
    projB_kernel<<<dim3(8, 24), 128>>>(Wo);
    assemble_kernel<<<BB * NN * 2, 256>>>(bo, attn_out, out);
}

// round 5
// speedup vs baseline: 4.2025x; 1.1591x over previous
#include <cuda_runtime.h>
#include <math.h>
#include <stdint.h>

#define BB 2
#define NN 128
#define HH 2
#define DM 512
#define DK 256
#define BHN 512
#define SCALE 0.005524271728019903f   // 1/sqrt(128*256)
#define OUT_ELEMS (BB*NN*NN*DM)        // 16777216

__device__ float g_q[BHN*DK];
__device__ float g_k[BHN*DK];
__device__ float g_v[BHN*DK];
__device__ float g_bx[BB*NN*DK];
__device__ float g_A[BHN];
__device__ float g_Bq[BHN];
__device__ float g_Ck[BHN];
__device__ float g_Dd[BB*NN];
__device__ float g_Vw[BHN*2*DM];       // [(bh,j)][hp][o]
__device__ float g_Bw[BB*NN*2*DM];     // [(b,j)][hp][o]

__device__ __forceinline__ float to_tf32(float x) {
    float r; asm("cvt.rna.tf32.f32 %0, %1;" : "=f"(r) : "f"(x)); return r;
}
__device__ __forceinline__ void mma_tf32(float* c,
        uint32_t a0, uint32_t a1, uint32_t a2, uint32_t a3,
        uint32_t b0, uint32_t b1) {
    asm volatile("mma.sync.aligned.m16n8k8.row.col.f32.tf32.tf32.f32 "
        "{%0,%1,%2,%3},{%4,%5,%6,%7},{%8,%9},{%0,%1,%2,%3};"
        : "+f"(c[0]), "+f"(c[1]), "+f"(c[2]), "+f"(c[3])
        : "r"(a0), "r"(a1), "r"(a2), "r"(a3), "r"(b0), "r"(b1));
}

// ---------------------------------------------------------------------------
// tf32 64x64 block GEMM core. 128 threads (4 warps 2x2), warp tile 32x32.
// ---------------------------------------------------------------------------
struct TCSmem {
    float sA[2][16][72];
    float sB[2][16][72];
};

template<int K>
__device__ __forceinline__ void gemm_tile_tc(const float* __restrict__ A,
        const float* __restrict__ W, int wcols, int row0, int col0,
        TCSmem& s, float cacc[2][4][4])
{
    const int t = threadIdx.x;
    const int lane = t & 31, warp = t >> 5;
    const int wm = (warp & 1) * 32, wn = (warp >> 1) * 32;
    const int gid = lane >> 2, tig = lane & 3;
    const int a_r = t >> 2, a_q = t & 3;
    const int b_k = t >> 4, b_q = t & 15;
    constexpr int NK = K / 16;

    float4 ra[2], rb[2];
#pragma unroll
    for (int l = 0; l < 2; ++l) {
        ra[l] = *(const float4*)&A[(size_t)(row0 + a_r + 32 * l) * K + a_q * 4];
        rb[l] = *(const float4*)&W[(size_t)(b_k + 8 * l) * wcols + col0 + b_q * 4];
    }
#pragma unroll
    for (int l = 0; l < 2; ++l) {
        int r = a_r + 32 * l, kq = a_q * 4;
        s.sA[0][kq + 0][r] = to_tf32(ra[l].x);
        s.sA[0][kq + 1][r] = to_tf32(ra[l].y);
        s.sA[0][kq + 2][r] = to_tf32(ra[l].z);
        s.sA[0][kq + 3][r] = to_tf32(ra[l].w);
        int kk = b_k + 8 * l, nq = b_q * 4;
        s.sB[0][kk][nq + 0] = to_tf32(rb[l].x);
        s.sB[0][kk][nq + 1] = to_tf32(rb[l].y);
        s.sB[0][kk][nq + 2] = to_tf32(rb[l].z);
        s.sB[0][kk][nq + 3] = to_tf32(rb[l].w);
    }
    __syncthreads();

#pragma unroll
    for (int kt = 0; kt < NK; ++kt) {
        const int cur = kt & 1, nxt = cur ^ 1;
        if (kt + 1 < NK) {
            int k0 = (kt + 1) * 16;
#pragma unroll
            for (int l = 0; l < 2; ++l) {
                ra[l] = *(const float4*)&A[(size_t)(row0 + a_r + 32 * l) * K + k0 + a_q * 4];
                rb[l] = *(const float4*)&W[(size_t)(k0 + b_k + 8 * l) * wcols + col0 + b_q * 4];
            }
        }
#pragma unroll
        for (int kf = 0; kf < 16; kf += 8) {
            uint32_t af[2][4], bf[4][2];
#pragma unroll
            for (int mi = 0; mi < 2; ++mi) {
                int m0 = wm + mi * 16 + gid;
                af[mi][0] = __float_as_uint(s.sA[cur][kf + tig][m0]);
                af[mi][1] = __float_as_uint(s.sA[cur][kf + tig][m0 + 8]);
                af[mi][2] = __float_as_uint(s.sA[cur][kf + tig + 4][m0]);
                af[mi][3] = __float_as_uint(s.sA[cur][kf + tig + 4][m0 + 8]);
            }
#pragma unroll
            for (int ni = 0; ni < 4; ++ni) {
                int n0 = wn + ni * 8 + gid;
                bf[ni][0] = __float_as_uint(s.sB[cur][kf + tig][n0]);
                bf[ni][1] = __float_as_uint(s.sB[cur][kf + tig + 4][n0]);
            }
#pragma unroll
            for (int mi = 0; mi < 2; ++mi)
#pragma unroll
                for (int ni = 0; ni < 4; ++ni)
                    mma_tf32(cacc[mi][ni], af[mi][0], af[mi][1], af[mi][2], af[mi][3],
                             bf[ni][0], bf[ni][1]);
        }
        if (kt + 1 < NK) {
#pragma unroll
            for (int l = 0; l < 2; ++l) {
                int r = a_r + 32 * l, kq = a_q * 4;
                s.sA[nxt][kq + 0][r] = to_tf32(ra[l].x);
                s.sA[nxt][kq + 1][r] = to_tf32(ra[l].y);
                s.sA[nxt][kq + 2][r] = to_tf32(ra[l].z);
                s.sA[nxt][kq + 3][r] = to_tf32(ra[l].w);
                int kk = b_k + 8 * l, nq = b_q * 4;
                s.sB[nxt][kk][nq + 0] = to_tf32(rb[l].x);
                s.sB[nxt][kk][nq + 1] = to_tf32(rb[l].y);
                s.sB[nxt][kk][nq + 2] = to_tf32(rb[l].z);
                s.sB[nxt][kk][nq + 3] = to_tf32(rb[l].w);
            }
        }
        __syncthreads();
    }
}

// ---------------------------------------------------------------------------
// Stage A: fused q/k/v/bx projections. grid=(28,4), 128 threads.
// ---------------------------------------------------------------------------
__global__ __launch_bounds__(128) void projA_kernel(
    const float* __restrict__ query, const float* __restrict__ key,
    const float* __restrict__ value, const float* __restrict__ boxes,
    const float* __restrict__ Wq, const float* __restrict__ bq,
    const float* __restrict__ Wk, const float* __restrict__ bk,
    const float* __restrict__ Wv, const float* __restrict__ bv,
    const float* __restrict__ Wbox, const float* __restrict__ bbox)
{
    __shared__ TCSmem s;
    int ct = blockIdx.x;
    int which = ct >> 3;
    int col0 = (ct - which * 8) * 64;
    int row0 = blockIdx.y * 64;

    const float* A; const float* W; const float* bias; float* out; int wcols;
    if      (which == 0) { A = query; W = Wq;   bias = bq;   out = g_q;  wcols = DM; }
    else if (which == 1) { A = key;   W = Wk;   bias = bk;   out = g_k;  wcols = DM; }
    else if (which == 2) { A = value; W = Wv;   bias = bv;   out = g_v;  wcols = DM; }
    else                 { A = boxes; W = Wbox; bias = bbox; out = g_bx; wcols = DK; }

    float cacc[2][4][4];
#pragma unroll
    for (int mi = 0; mi < 2; ++mi)
#pragma unroll
        for (int ni = 0; ni < 4; ++ni)
#pragma unroll
            for (int r = 0; r < 4; ++r) cacc[mi][ni][r] = 0.f;

    gemm_tile_tc<DM>(A, W, wcols, row0, col0, s, cacc);

    const int lane = threadIdx.x & 31, warp = threadIdx.x >> 5;
    const int wm = (warp & 1) * 32, wn = (warp >> 1) * 32;
    const int gid = lane >> 2, tig = lane & 3;
#pragma unroll
    for (int mi = 0; mi < 2; ++mi)
#pragma unroll
        for (int rr = 0; rr < 2; ++rr) {
            int row = row0 + wm + mi * 16 + rr * 8 + gid;
            int b = row >> 7, n = row & 127;
#pragma unroll
            for (int ni = 0; ni < 4; ++ni) {
                int col = col0 + wn + ni * 8 + tig * 2;
                float2 v;
                v.x = cacc[mi][ni][rr * 2 + 0] + bias[col];
                v.y = cacc[mi][ni][rr * 2 + 1] + bias[col + 1];
                if (which < 3) {
                    int h = col >> 8, dk = col & 255;
                    *(float2*)&out[(((b * HH + h) * NN) + n) * DK + dk] = v;
                } else {
                    *(float2*)&out[row * DK + col] = v;
                }
            }
        }
}

// ---------------------------------------------------------------------------
// Fused Stage B + dots. Blocks 0..191: projB tiles. Blocks 192..319: dots.
// 128 threads per block.
// ---------------------------------------------------------------------------
__global__ __launch_bounds__(128) void projB_dots_kernel(const float* __restrict__ Wo)
{
    __shared__ TCSmem s;
    int p = blockIdx.x;

    if (p >= 192) {
        // ---- dots: warp per j ----
        int w = threadIdx.x >> 5;
        int lane = threadIdx.x & 31;
        int bid = (p - 192) * 4 + w;   // bh*N + j, 0..511
        int j = bid & 127;
        int bh = bid >> 7;
        int b = bh >> 1;

        const float4* qr = (const float4*)(g_q  + (size_t)bid * DK);
        const float4* kr = (const float4*)(g_k  + (size_t)bid * DK);
        const float4* br = (const float4*)(g_bx + (size_t)(b * NN + j) * DK);

        float pa = 0.f, pb = 0.f, pc = 0.f, pd = 0.f;
#pragma unroll
        for (int u = 0; u < 2; ++u) {
            int d = lane + u * 32;
            float4 qv = qr[d], kv = kr[d], bv = br[d];
            pa += qv.x*kv.x + qv.y*kv.y + qv.z*kv.z + qv.w*kv.w;
            pb += bv.x*kv.x + bv.y*kv.y + bv.z*kv.z + bv.w*kv.w;
            pc += qv.x*bv.x + qv.y*bv.y + qv.z*bv.z + qv.w*bv.w;
            pd += bv.x*bv.x + bv.y*bv.y + bv.z*bv.z + bv.w*bv.w;
        }
#pragma unroll
        for (int off = 16; off > 0; off >>= 1) {
            pa += __shfl_down_sync(0xffffffff, pa, off);
            pb += __shfl_down_sync(0xffffffff, pb, off);
            pc += __shfl_down_sync(0xffffffff, pc, off);
            pd += __shfl_down_sync(0xffffffff, pd, off);
        }
        if (lane == 0) {
            g_A[bid] = pa;
            g_Bq[bid] = pb;
            g_Ck[bid] = pc;
            if ((bh & 1) == 0) g_Dd[b * NN + j] = pd;
        }
        return;
    }

    // ---- projB tile ----
    int y = p >> 3;
    int col0 = (p & 7) * 64;
    const float* A; float* out; int row0, hp;
    if (y < 16) { A = g_v;  out = g_Vw; hp = y >> 3; row0 = (y & 7) * 64; }
    else        { y -= 16; A = g_bx; out = g_Bw; hp = y >> 2; row0 = (y & 3) * 64; }
    const float* W = Wo + (size_t)hp * DK * DM;

    float cacc[2][4][4];
#pragma unroll
    for (int mi = 0; mi < 2; ++mi)
#pragma unroll
        for (int ni = 0; ni < 4; ++ni)
#pragma unroll
            for (int r = 0; r < 4; ++r) cacc[mi][ni][r] = 0.f;

    gemm_tile_tc<DK>(A, W, DM, row0, col0, s, cacc);

    const int lane = threadIdx.x & 31, warp = threadIdx.x >> 5;
    const int wm = (warp & 1) * 32, wn = (warp >> 1) * 32;
    const int gid = lane >> 2, tig = lane & 3;
#pragma unroll
    for (int mi = 0; mi < 2; ++mi)
#pragma unroll
        for (int rr = 0; rr < 2; ++rr) {
            int row = row0 + wm + mi * 16 + rr * 8 + gid;
#pragma unroll
            for (int ni = 0; ni < 4; ++ni) {
                int col = col0 + wn + ni * 8 + tig * 2;
                float2 v;
                v.x = cacc[mi][ni][rr * 2 + 0];
                v.y = cacc[mi][ni][rr * 2 + 1];
                *(float2*)&out[(size_t)row * (2 * DM) + hp * DM + col] = v;
            }
        }
}

// ---------------------------------------------------------------------------
// Softmax: grid 128, 128 threads, warp per row (4 rows per block).
// ---------------------------------------------------------------------------
__global__ __launch_bounds__(128) void softmax_kernel(float* __restrict__ attn_out)
{
    int warp = threadIdx.x >> 5, lane = threadIdx.x & 31;
    int t = threadIdx.x;
    int row_base = blockIdx.x * 4;       // rows = bh*128 + n; 4 per block
    int bh = row_base >> 7;
    int b = bh >> 1;

    __shared__ float sA[128], sCk[128];
    __shared__ float part[4];
    __shared__ float sS0;

    if (t < 128) {
        sA[t]  = g_A[bh * NN + t];
        sCk[t] = g_Ck[bh * NN + t];
    }
    __syncthreads();
    // S0
    {
        float v = sA[t];
#pragma unroll
        for (int off = 16; off > 0; off >>= 1)
            v += __shfl_down_sync(0xffffffff, v, off);
        if (lane == 0) part[warp] = v;
    }
    __syncthreads();
    if (t == 0) sS0 = part[0] + part[1] + part[2] + part[3];
    __syncthreads();
    float S0 = sS0;

    int n = (row_base & 127) + warp;
    float An = sA[n];
    float Bqn = g_Bq[bh * NN + n];
    float Ddn = g_Dd[b * NN + n];

    float sv[4], mx = -1e30f;
#pragma unroll
    for (int u = 0; u < 4; ++u) {
        int m = lane + u * 32;
        float x = (m == n) ? (S0 - An + Ddn)
                           : (S0 - An - sA[m] + Bqn + sCk[m]);
        sv[u] = x * SCALE;
        mx = fmaxf(mx, sv[u]);
    }
#pragma unroll
    for (int off = 16; off > 0; off >>= 1)
        mx = fmaxf(mx, __shfl_xor_sync(0xffffffff, mx, off));
    float e[4], tot = 0.f;
#pragma unroll
    for (int u = 0; u < 4; ++u) { e[u] = expf(sv[u] - mx); tot += e[u]; }
#pragma unroll
    for (int off = 16; off > 0; off >>= 1)
        tot += __shfl_xor_sync(0xffffffff, tot, off);
    float inv = 1.f / tot;
    size_t base = ((size_t)(bh * NN) + n) * NN;
#pragma unroll
    for (int u = 0; u < 4; ++u)
        attn_out[base + lane + u * 32] = e[u] * inv;
}

// ---------------------------------------------------------------------------
// Assembly: block per (b, jp, iq). 1024 blocks x 256 thr, 16 iters each.
// out[b,i,jp,:] = base + a0*d0 + a1*d1
// ---------------------------------------------------------------------------
__global__ __launch_bounds__(256) void assemble_kernel(
    const float* __restrict__ bo, const float* __restrict__ attn,
    float* __restrict__ out)
{
    int bid = blockIdx.x;          // ((b*128+jp)*4 + iq)
    int iq = bid & 3;
    int bjp = bid >> 2;
    int jp = bjp & 127, b = bjp >> 7;
    int h = jp >> 6, jj = jp & 63;
    int j0 = 2 * jj, j1 = j0 + 1;
    int bh = b * HH + h;

    __shared__ float sbase[512], sd0[512], sd1[512];
    __shared__ float sa[32][2];

    int t = threadIdx.x;
    for (int c = t; c < 512; c += 256) {
        float v0 = g_Vw[(size_t)((bh * NN + j0) * 2 + 0) * DM + c];
        float v1 = g_Vw[(size_t)((bh * NN + j1) * 2 + 1) * DM + c];
        float w0 = g_Bw[(size_t)((b  * NN + j0) * 2 + 0) * DM + c];
        float w1 = g_Bw[(size_t)((b  * NN + j1) * 2 + 1) * DM + c];
        sbase[c] = v0 + v1 + bo[c];
        sd0[c]   = w0 - v0;
        sd1[c]   = w1 - v1;
    }
    if (t < 64) {
        int i = iq * 32 + (t >> 1), w = t & 1;
        sa[t >> 1][w] = attn[((size_t)(bh * NN) + i) * NN + j0 + w];
    }
    __syncthreads();

    int sub = t >> 7;
    int c4 = (t & 127) * 4;
    float4 rb = *(const float4*)&sbase[c4];
    float4 r0 = *(const float4*)&sd0[c4];
    float4 r1 = *(const float4*)&sd1[c4];

#pragma unroll 4
    for (int it = 0; it < 16; ++it) {
        int il = it * 2 + sub;
        int i = iq * 32 + il;
        float a0 = sa[il][0], a1 = sa[il][1];
        float4 r;
        r.x = rb.x + a0 * r0.x + a1 * r1.x;
        r.y = rb.y + a0 * r0.y + a1 * r1.y;
        r.z = rb.z + a0 * r0.z + a1 * r1.z;
        r.w = rb.w + a0 * r0.w + a1 * r1.w;
        *(float4*)&out[(((size_t)(b * NN + i) * NN) + jp) * DM + c4] = r;
    }
}

// ---------------------------------------------------------------------------
extern "C" void kernel_launch(void* const* d_in, const int* in_sizes, int n_in,
                              void* d_out, int out_size)
{
    const float* query = (const float*)d_in[0];
    const float* key   = (const float*)d_in[1];
    const float* value = (const float*)d_in[2];
    const float* boxes = (const float*)d_in[3];
    const float* Wq = (const float*)d_in[4];
    const float* bq = (const float*)d_in[5];
    const float* Wk = (const float*)d_in[6];
    const float* bk = (const float*)d_in[7];
    const float* Wv = (const float*)d_in[8];
    const float* bv = (const float*)d_in[9];
    const float* Wbox = (const float*)d_in[10];
    const float* bbox = (const float*)d_in[11];
    const float* Wo = (const float*)d_in[12];
    const float* bo = (const float*)d_in[13];

    float* out = (float*)d_out;
    float* attn_out = out + OUT_ELEMS;

    projA_kernel<<<dim3(28, 4), 128>>>(query, key, value, boxes,
                                       Wq, bq, Wk, bk, Wv, bv, Wbox, bbox);
    projB_dots_kernel<<<320, 128>>>(Wo);
    softmax_kernel<<<128, 128>>>(attn_out);
    assemble_kernel<<<BB * NN * 4, 256>>>(bo, attn_out, out);
}

// round 6
// speedup vs baseline: 4.7395x; 1.1278x over previous
#include <cuda_runtime.h>
#include <math.h>
#include <stdint.h>

#define BB 2
#define NN 128
#define HH 2
#define DM 512
#define DK 256
#define BHN 512
#define SCALE 0.005524271728019903f   // 1/sqrt(128*256)
#define OUT_ELEMS (BB*NN*NN*DM)        // 16777216

__device__ float g_q[BHN*DK];
__device__ float g_k[BHN*DK];
__device__ float g_v[BHN*DK];
__device__ float g_bx[BB*NN*DK];
__device__ float g_A[BHN];
__device__ float g_Bq[BHN];
__device__ float g_Ck[BHN];
__device__ float g_Dd[BB*NN];
__device__ float g_Vw[BHN*2*DM];       // [(bh,j)][hp][o]
__device__ float g_Bw[BB*NN*2*DM];     // [(b,j)][hp][o]

__device__ __forceinline__ float to_tf32(float x) {
    float r; asm("cvt.rna.tf32.f32 %0, %1;" : "=f"(r) : "f"(x)); return r;
}
__device__ __forceinline__ void mma_tf32(float* c,
        uint32_t a0, uint32_t a1, uint32_t a2, uint32_t a3,
        uint32_t b0, uint32_t b1) {
    asm volatile("mma.sync.aligned.m16n8k8.row.col.f32.tf32.tf32.f32 "
        "{%0,%1,%2,%3},{%4,%5,%6,%7},{%8,%9},{%0,%1,%2,%3};"
        : "+f"(c[0]), "+f"(c[1]), "+f"(c[2]), "+f"(c[3])
        : "r"(a0), "r"(a1), "r"(a2), "r"(a3), "r"(b0), "r"(b1));
}

// ---------------------------------------------------------------------------
// tf32 64x64 block GEMM core. 256 threads (8 warps, 2x4), warp tile 32x16.
// k-tile 32, double-buffered.
// ---------------------------------------------------------------------------
struct TCSmem {
    float sA[2][32][72];
    float sB[2][32][72];
};

template<int K>
__device__ __forceinline__ void gemm_tile_tc(const float* __restrict__ A,
        const float* __restrict__ W, int wcols, int row0, int col0,
        TCSmem& s, float cacc[2][2][4])
{
    const int t = threadIdx.x;
    const int lane = t & 31, warp = t >> 5;
    const int wm = (warp & 1) * 32, wn = (warp >> 1) * 16;
    const int gid = lane >> 2, tig = lane & 3;
    const int a_r = t >> 3;           // 0..31 (+32*l)
    const int a_q = (t & 7) * 4;      // k base 0..28
    const int b_k = t >> 4;           // 0..15 (+16*l)
    const int b_q = (t & 15) * 4;     // n base 0..60
    constexpr int NK = K / 32;

    float4 ra[2], rb[2];
#pragma unroll
    for (int l = 0; l < 2; ++l) {
        ra[l] = *(const float4*)&A[(size_t)(row0 + a_r + 32 * l) * K + a_q];
        rb[l] = *(const float4*)&W[(size_t)(b_k + 16 * l) * wcols + col0 + b_q];
    }
#pragma unroll
    for (int l = 0; l < 2; ++l) {
        int r = a_r + 32 * l;
        s.sA[0][a_q + 0][r] = to_tf32(ra[l].x);
        s.sA[0][a_q + 1][r] = to_tf32(ra[l].y);
        s.sA[0][a_q + 2][r] = to_tf32(ra[l].z);
        s.sA[0][a_q + 3][r] = to_tf32(ra[l].w);
        float4 tb;
        tb.x = to_tf32(rb[l].x); tb.y = to_tf32(rb[l].y);
        tb.z = to_tf32(rb[l].z); tb.w = to_tf32(rb[l].w);
        *(float4*)&s.sB[0][b_k + 16 * l][b_q] = tb;
    }
    __syncthreads();

#pragma unroll
    for (int kt = 0; kt < NK; ++kt) {
        const int cur = kt & 1, nxt = cur ^ 1;
        if (kt + 1 < NK) {
            int k0 = (kt + 1) * 32;
#pragma unroll
            for (int l = 0; l < 2; ++l) {
                ra[l] = *(const float4*)&A[(size_t)(row0 + a_r + 32 * l) * K + k0 + a_q];
                rb[l] = *(const float4*)&W[(size_t)(k0 + b_k + 16 * l) * wcols + col0 + b_q];
            }
        }
#pragma unroll
        for (int kf = 0; kf < 32; kf += 8) {
            uint32_t af[2][4], bf[2][2];
#pragma unroll
            for (int mi = 0; mi < 2; ++mi) {
                int m0 = wm + mi * 16 + gid;
                af[mi][0] = __float_as_uint(s.sA[cur][kf + tig][m0]);
                af[mi][1] = __float_as_uint(s.sA[cur][kf + tig][m0 + 8]);
                af[mi][2] = __float_as_uint(s.sA[cur][kf + tig + 4][m0]);
                af[mi][3] = __float_as_uint(s.sA[cur][kf + tig + 4][m0 + 8]);
            }
#pragma unroll
            for (int ni = 0; ni < 2; ++ni) {
                int n0 = wn + ni * 8 + gid;
                bf[ni][0] = __float_as_uint(s.sB[cur][kf + tig][n0]);
                bf[ni][1] = __float_as_uint(s.sB[cur][kf + tig + 4][n0]);
            }
#pragma unroll
            for (int mi = 0; mi < 2; ++mi)
#pragma unroll
                for (int ni = 0; ni < 2; ++ni)
                    mma_tf32(cacc[mi][ni], af[mi][0], af[mi][1], af[mi][2], af[mi][3],
                             bf[ni][0], bf[ni][1]);
        }
        if (kt + 1 < NK) {
#pragma unroll
            for (int l = 0; l < 2; ++l) {
                int r = a_r + 32 * l;
                s.sA[nxt][a_q + 0][r] = to_tf32(ra[l].x);
                s.sA[nxt][a_q + 1][r] = to_tf32(ra[l].y);
                s.sA[nxt][a_q + 2][r] = to_tf32(ra[l].z);
                s.sA[nxt][a_q + 3][r] = to_tf32(ra[l].w);
                float4 tb;
                tb.x = to_tf32(rb[l].x); tb.y = to_tf32(rb[l].y);
                tb.z = to_tf32(rb[l].z); tb.w = to_tf32(rb[l].w);
                *(float4*)&s.sB[nxt][b_k + 16 * l][b_q] = tb;
            }
        }
        __syncthreads();
    }
}

// ---------------------------------------------------------------------------
// Stage A: fused q/k/v/bx projections. grid=(28,4), 256 threads.
// ---------------------------------------------------------------------------
__global__ __launch_bounds__(256) void projA_kernel(
    const float* __restrict__ query, const float* __restrict__ key,
    const float* __restrict__ value, const float* __restrict__ boxes,
    const float* __restrict__ Wq, const float* __restrict__ bq,
    const float* __restrict__ Wk, const float* __restrict__ bk,
    const float* __restrict__ Wv, const float* __restrict__ bv,
    const float* __restrict__ Wbox, const float* __restrict__ bbox)
{
    __shared__ TCSmem s;
    int ct = blockIdx.x;
    int which = ct >> 3;
    int col0 = (ct - which * 8) * 64;
    int row0 = blockIdx.y * 64;

    const float* A; const float* W; const float* bias; float* out; int wcols;
    if      (which == 0) { A = query; W = Wq;   bias = bq;   out = g_q;  wcols = DM; }
    else if (which == 1) { A = key;   W = Wk;   bias = bk;   out = g_k;  wcols = DM; }
    else if (which == 2) { A = value; W = Wv;   bias = bv;   out = g_v;  wcols = DM; }
    else                 { A = boxes; W = Wbox; bias = bbox; out = g_bx; wcols = DK; }

    float cacc[2][2][4];
#pragma unroll
    for (int mi = 0; mi < 2; ++mi)
#pragma unroll
        for (int ni = 0; ni < 2; ++ni)
#pragma unroll
            for (int r = 0; r < 4; ++r) cacc[mi][ni][r] = 0.f;

    gemm_tile_tc<DM>(A, W, wcols, row0, col0, s, cacc);

    const int lane = threadIdx.x & 31, warp = threadIdx.x >> 5;
    const int wm = (warp & 1) * 32, wn = (warp >> 1) * 16;
    const int gid = lane >> 2, tig = lane & 3;
#pragma unroll
    for (int mi = 0; mi < 2; ++mi)
#pragma unroll
        for (int rr = 0; rr < 2; ++rr) {
            int row = row0 + wm + mi * 16 + rr * 8 + gid;
            int b = row >> 7, n = row & 127;
#pragma unroll
            for (int ni = 0; ni < 2; ++ni) {
                int col = col0 + wn + ni * 8 + tig * 2;
                float2 v;
                v.x = cacc[mi][ni][rr * 2 + 0] + bias[col];
                v.y = cacc[mi][ni][rr * 2 + 1] + bias[col + 1];
                if (which < 3) {
                    int h = col >> 8, dk = col & 255;
                    *(float2*)&out[(((b * HH + h) * NN) + n) * DK + dk] = v;
                } else {
                    *(float2*)&out[row * DK + col] = v;
                }
            }
        }
}

// ---------------------------------------------------------------------------
// Fused Stage B + dots. Blocks 0..191: projB tiles. Blocks 192..255: dots.
// 256 threads.
// ---------------------------------------------------------------------------
__global__ __launch_bounds__(256) void projB_dots_kernel(const float* __restrict__ Wo)
{
    __shared__ TCSmem s;
    int p = blockIdx.x;

    if (p >= 192) {
        // ---- dots: warp per j (8 per block) ----
        int w = threadIdx.x >> 5;
        int lane = threadIdx.x & 31;
        int bid = (p - 192) * 8 + w;   // bh*N + j, 0..511
        int j = bid & 127;
        int bh = bid >> 7;
        int b = bh >> 1;

        const float4* qr = (const float4*)(g_q  + (size_t)bid * DK);
        const float4* kr = (const float4*)(g_k  + (size_t)bid * DK);
        const float4* br = (const float4*)(g_bx + (size_t)(b * NN + j) * DK);

        float pa = 0.f, pb = 0.f, pc = 0.f, pd = 0.f;
#pragma unroll
        for (int u = 0; u < 2; ++u) {
            int d = lane + u * 32;
            float4 qv = qr[d], kv = kr[d], bv = br[d];
            pa += qv.x*kv.x + qv.y*kv.y + qv.z*kv.z + qv.w*kv.w;
            pb += bv.x*kv.x + bv.y*kv.y + bv.z*kv.z + bv.w*kv.w;
            pc += qv.x*bv.x + qv.y*bv.y + qv.z*bv.z + qv.w*bv.w;
            pd += bv.x*bv.x + bv.y*bv.y + bv.z*bv.z + bv.w*bv.w;
        }
#pragma unroll
        for (int off = 16; off > 0; off >>= 1) {
            pa += __shfl_down_sync(0xffffffff, pa, off);
            pb += __shfl_down_sync(0xffffffff, pb, off);
            pc += __shfl_down_sync(0xffffffff, pc, off);
            pd += __shfl_down_sync(0xffffffff, pd, off);
        }
        if (lane == 0) {
            g_A[bid] = pa;
            g_Bq[bid] = pb;
            g_Ck[bid] = pc;
            if ((bh & 1) == 0) g_Dd[b * NN + j] = pd;
        }
        return;
    }

    // ---- projB tile ----
    int y = p >> 3;
    int col0 = (p & 7) * 64;
    const float* A; float* out; int row0, hp;
    if (y < 16) { A = g_v;  out = g_Vw; hp = y >> 3; row0 = (y & 7) * 64; }
    else        { y -= 16; A = g_bx; out = g_Bw; hp = y >> 2; row0 = (y & 3) * 64; }
    const float* W = Wo + (size_t)hp * DK * DM;

    float cacc[2][2][4];
#pragma unroll
    for (int mi = 0; mi < 2; ++mi)
#pragma unroll
        for (int ni = 0; ni < 2; ++ni)
#pragma unroll
            for (int r = 0; r < 4; ++r) cacc[mi][ni][r] = 0.f;

    gemm_tile_tc<DK>(A, W, DM, row0, col0, s, cacc);

    const int lane = threadIdx.x & 31, warp = threadIdx.x >> 5;
    const int wm = (warp & 1) * 32, wn = (warp >> 1) * 16;
    const int gid = lane >> 2, tig = lane & 3;
#pragma unroll
    for (int mi = 0; mi < 2; ++mi)
#pragma unroll
        for (int rr = 0; rr < 2; ++rr) {
            int row = row0 + wm + mi * 16 + rr * 8 + gid;
#pragma unroll
            for (int ni = 0; ni < 2; ++ni) {
                int col = col0 + wn + ni * 8 + tig * 2;
                float2 v;
                v.x = cacc[mi][ni][rr * 2 + 0];
                v.y = cacc[mi][ni][rr * 2 + 1];
                *(float2*)&out[(size_t)row * (2 * DM) + hp * DM + col] = v;
            }
        }
}

// ---------------------------------------------------------------------------
// Softmax: grid 128, 128 threads, warp per row (4 rows per block).
// ---------------------------------------------------------------------------
__global__ __launch_bounds__(128) void softmax_kernel(float* __restrict__ attn_out)
{
    int warp = threadIdx.x >> 5, lane = threadIdx.x & 31;
    int t = threadIdx.x;
    int row_base = blockIdx.x * 4;
    int bh = row_base >> 7;
    int b = bh >> 1;

    __shared__ float sA[128], sCk[128];
    __shared__ float part[4];
    __shared__ float sS0;

    sA[t]  = g_A[bh * NN + t];
    sCk[t] = g_Ck[bh * NN + t];
    __syncthreads();
    {
        float v = sA[t];
#pragma unroll
        for (int off = 16; off > 0; off >>= 1)
            v += __shfl_down_sync(0xffffffff, v, off);
        if (lane == 0) part[warp] = v;
    }
    __syncthreads();
    if (t == 0) sS0 = part[0] + part[1] + part[2] + part[3];
    __syncthreads();
    float S0 = sS0;

    int n = (row_base & 127) + warp;
    float An = sA[n];
    float Bqn = g_Bq[bh * NN + n];
    float Ddn = g_Dd[b * NN + n];

    float sv[4], mx = -1e30f;
#pragma unroll
    for (int u = 0; u < 4; ++u) {
        int m = lane + u * 32;
        float x = (m == n) ? (S0 - An + Ddn)
                           : (S0 - An - sA[m] + Bqn + sCk[m]);
        sv[u] = x * SCALE;
        mx = fmaxf(mx, sv[u]);
    }
#pragma unroll
    for (int off = 16; off > 0; off >>= 1)
        mx = fmaxf(mx, __shfl_xor_sync(0xffffffff, mx, off));
    float e[4], tot = 0.f;
#pragma unroll
    for (int u = 0; u < 4; ++u) { e[u] = expf(sv[u] - mx); tot += e[u]; }
#pragma unroll
    for (int off = 16; off > 0; off >>= 1)
        tot += __shfl_xor_sync(0xffffffff, tot, off);
    float inv = 1.f / tot;
    size_t base = ((size_t)(bh * NN) + n) * NN;
#pragma unroll
    for (int u = 0; u < 4; ++u)
        attn_out[base + lane + u * 32] = e[u] * inv;
}

// ---------------------------------------------------------------------------
// Assembly: sync-free, zero smem. Block per (b, jp, iq): 1024 x 256.
// Per-iter attn coefficients broadcast via shfl; base/d0/d1 in registers.
// out[b,i,jp,:] = base + a0*d0 + a1*d1
// ---------------------------------------------------------------------------
__global__ __launch_bounds__(256) void assemble_kernel(
    const float* __restrict__ bo, const float* __restrict__ attn,
    float* __restrict__ out)
{
    int bid = blockIdx.x;          // ((b*128+jp)*4 + iq)
    int iq = bid & 3;
    int bjp = bid >> 2;
    int jp = bjp & 127, b = bjp >> 7;
    int h = jp >> 6, jj = jp & 63;
    int j0 = 2 * jj, j1 = j0 + 1;
    int bh = b * HH + h;

    int t = threadIdx.x;
    int lane = t & 31;
    int sub = t >> 7;              // constant within a warp
    int c4 = (t & 127) * 4;

    float4 v0 = *(const float4*)&g_Vw[(size_t)((bh * NN + j0) * 2 + 0) * DM + c4];
    float4 v1 = *(const float4*)&g_Vw[(size_t)((bh * NN + j1) * 2 + 1) * DM + c4];
    float4 w0 = *(const float4*)&g_Bw[(size_t)((b  * NN + j0) * 2 + 0) * DM + c4];
    float4 w1 = *(const float4*)&g_Bw[(size_t)((b  * NN + j1) * 2 + 1) * DM + c4];
    float4 bb = *(const float4*)&bo[c4];

    float4 rb, r0, r1;
    rb.x = v0.x + v1.x + bb.x; rb.y = v0.y + v1.y + bb.y;
    rb.z = v0.z + v1.z + bb.z; rb.w = v0.w + v1.w + bb.w;
    r0.x = w0.x - v0.x; r0.y = w0.y - v0.y; r0.z = w0.z - v0.z; r0.w = w0.w - v0.w;
    r1.x = w1.x - v1.x; r1.y = w1.y - v1.y; r1.z = w1.z - v1.z; r1.w = w1.w - v1.w;

    // lane l<16 holds a0 for iter l; lane>=16 holds a1 for iter l-16
    int itn = lane & 15;
    int i_pre = iq * 32 + itn * 2 + sub;
    float aval = attn[((size_t)(bh * NN) + i_pre) * NN + j0 + (lane >> 4)];

#pragma unroll
    for (int it = 0; it < 16; ++it) {
        float a0 = __shfl_sync(0xffffffff, aval, it);
        float a1 = __shfl_sync(0xffffffff, aval, it + 16);
        int i = iq * 32 + it * 2 + sub;
        float4 r;
        r.x = rb.x + a0 * r0.x + a1 * r1.x;
        r.y = rb.y + a0 * r0.y + a1 * r1.y;
        r.z = rb.z + a0 * r0.z + a1 * r1.z;
        r.w = rb.w + a0 * r0.w + a1 * r1.w;
        *(float4*)&out[(((size_t)(b * NN + i) * NN) + jp) * DM + c4] = r;
    }
}

// ---------------------------------------------------------------------------
extern "C" void kernel_launch(void* const* d_in, const int* in_sizes, int n_in,
                              void* d_out, int out_size)
{
    const float* query = (const float*)d_in[0];
    const float* key   = (const float*)d_in[1];
    const float* value = (const float*)d_in[2];
    const float* boxes = (const float*)d_in[3];
    const float* Wq = (const float*)d_in[4];
    const float* bq = (const float*)d_in[5];
    const float* Wk = (const float*)d_in[6];
    const float* bk = (const float*)d_in[7];
    const float* Wv = (const float*)d_in[8];
    const float* bv = (const float*)d_in[9];
    const float* Wbox = (const float*)d_in[10];
    const float* bbox = (const float*)d_in[11];
    const float* Wo = (const float*)d_in[12];
    const float* bo = (const float*)d_in[13];

    float* out = (float*)d_out;
    float* attn_out = out + OUT_ELEMS;

    projA_kernel<<<dim3(28, 4), 256>>>(query, key, value, boxes,
                                       Wq, bq, Wk, bk, Wv, bv, Wbox, bbox);
    projB_dots_kernel<<<256, 256>>>(Wo);
    softmax_kernel<<<128, 128>>>(attn_out);
    assemble_kernel<<<BB * NN * 4, 256>>>(bo, attn_out, out);
}